// round 9
// baseline (speedup 1.0000x reference)
#include <cuda_runtime.h>
#include <cstdint>

// Problem constants
#define BSZ     8
#define KDIM    4096
#define NDIM    11008
#define RPW     8                        // rows per warp task
#define SPLITK  8
#define KCH     (KDIM / SPLITK)          // 512 floats per K-chunk
#define KITERS  (KCH / 128)              // 4 iterations (128 k per iter)
#define WARPS_PER_CTA 16
#define THREADS (WARPS_PER_CTA * 32)     // 512
#define NCTAS   148
#define TOTAL_WARPS (NCTAS * WARPS_PER_CTA)   // 2368
#define NROWGROUPS (NDIM / RPW)               // 1376
#define NTASKS  (NROWGROUPS * SPLITK)         // 11008
#define SMEM_BYTES (BSZ * KDIM * 4)           // 131072 (xT, swizzled)

// Split-K partial sums: [SPLITK][BSZ][NDIM]
__device__ float g_partial[SPLITK * BSZ * NDIM];

typedef unsigned long long ull;

// ---- packed f32x2 ops (Blackwell f32x2 pipe) ----
__device__ __forceinline__ void ffma2(ull& d, ull a, ull b) {
    asm("fma.rn.f32x2 %0, %1, %2, %0;" : "+l"(d) : "l"(a), "l"(b));
}
__device__ __forceinline__ ull addf32x2(ull a, ull b) {
    ull r;
    asm("add.rn.f32x2 %0, %1, %2;" : "=l"(r) : "l"(a), "l"(b));
    return r;
}
__device__ __forceinline__ ull pk2(float lo, float hi) {
    ull r;
    asm("mov.b64 %0, {%1, %2};" : "=l"(r) : "f"(lo), "f"(hi));
    return r;
}
__device__ __forceinline__ void unpk2(ull a, float& lo, float& hi) {
    asm("mov.b64 {%0, %1}, %2;" : "=f"(lo), "=f"(hi) : "l"(a));
}
// streaming 128-bit weight load (bypass L1 reuse)
__device__ __forceinline__ float4 ldg_cs_f4(const float* p) {
    float4 v;
    asm("ld.global.cs.v4.f32 {%0, %1, %2, %3}, [%4];"
        : "=f"(v.x), "=f"(v.y), "=f"(v.z), "=f"(v.w) : "l"(p));
    return v;
}
__device__ __forceinline__ uint32_t smem_u32(const void* p) {
    uint32_t a;
    asm("{ .reg .u64 t; cvta.to.shared.u64 t, %1; cvt.u32.u64 %0, t; }"
        : "=r"(a) : "l"(p));
    return a;
}
__device__ __forceinline__ void lds_v2u64(uint32_t addr, ull& a, ull& b) {
    asm volatile("ld.shared.v2.u64 {%0, %1}, [%2];"
                 : "=l"(a), "=l"(b) : "r"(addr));
}
__device__ __forceinline__ uint32_t swz(uint32_t byte) {
    return byte ^ ((byte >> 3) & 0x70u);
}

extern __shared__ char xsm[];   // xT[k][b], 16B chunks SW128-swizzled

__global__ __launch_bounds__(THREADS, 1)
void asl_gemv_kernel(const float* __restrict__ x,
                     const float* __restrict__ w) {
    const int tid  = threadIdx.x;
    const int lane = tid & 31;

    // ---- stage x transposed+swizzled: xT[k][b] at swz(k*32 + b*4) ----
    {
        const float4* x4 = reinterpret_cast<const float4*>(x);
        #pragma unroll 4
        for (int i4 = tid; i4 < BSZ * KDIM / 4; i4 += THREADS) {
            const int b  = i4 >> 10;             // batch
            const int k0 = (i4 & 1023) * 4;      // first of 4 k
            float4 xv = x4[i4];
            *reinterpret_cast<float*>(xsm + swz((k0 + 0) * 32 + b * 4)) = xv.x;
            *reinterpret_cast<float*>(xsm + swz((k0 + 1) * 32 + b * 4)) = xv.y;
            *reinterpret_cast<float*>(xsm + swz((k0 + 2) * 32 + b * 4)) = xv.z;
            *reinterpret_cast<float*>(xsm + swz((k0 + 3) * 32 + b * 4)) = xv.w;
        }
    }
    __syncthreads();

    const uint32_t xbase = smem_u32(xsm);
    const int gwarp = blockIdx.x * WARPS_PER_CTA + (tid >> 5);

    for (int task = gwarp; task < NTASKS; task += TOTAL_WARPS) {
        const int rg    = task >> 3;          // row group
        const int kc    = task & 7;           // K-chunk
        const int n0    = rg * RPW;
        const int kbase = kc * KCH;

        const float* wr = w + (size_t)n0 * KDIM + kbase;

        // acc[r][p]: f32x2 packs batches (2p, 2p+1)
        ull acc[RPW][4];
        #pragma unroll
        for (int r = 0; r < RPW; r++)
            #pragma unroll
            for (int p = 0; p < 4; p++)
                acc[r][p] = 0ULL;

        #pragma unroll 1
        for (int it = 0; it < KITERS; it++) {
            const int k0 = it * 128 + lane * 4;       // within chunk

            float4 wv[RPW];
            #pragma unroll
            for (int r = 0; r < RPW; r++)
                wv[r] = ldg_cs_f4(wr + (size_t)r * KDIM + k0);

            const uint32_t kg32 = (uint32_t)(kbase + k0) * 32;  // byte base
            #pragma unroll
            for (int j = 0; j < 4; j++) {
                ull sp[RPW];
                #pragma unroll
                for (int r = 0; r < RPW; r++) {
                    const float wj = (j == 0) ? wv[r].x :
                                     (j == 1) ? wv[r].y :
                                     (j == 2) ? wv[r].z : wv[r].w;
                    sp[r] = pk2(wj, wj);
                }
                #pragma unroll
                for (int h = 0; h < 2; h++) {
                    const uint32_t byte = kg32 + (uint32_t)j * 32 + h * 16;
                    ull x0, x1;   // (b=4h,4h+1), (b=4h+2,4h+3)
                    lds_v2u64(xbase + swz(byte), x0, x1);
                    #pragma unroll
                    for (int r = 0; r < RPW; r++) {
                        ffma2(acc[r][2 * h],     sp[r], x0);
                        ffma2(acc[r][2 * h + 1], sp[r], x1);
                    }
                }
            }
        }

        // ---- butterfly epilogue on 32 packed pairs (each ULL = 2 batches) ----
        // v[i] <-> (r = i & 7, p = i >> 3); after 5 rounds lane l holds v[l].
        ull v[32];
        #pragma unroll
        for (int p = 0; p < 4; p++)
            #pragma unroll
            for (int r = 0; r < RPW; r++)
                v[p * 8 + r] = acc[r][p];

        #pragma unroll
        for (int s = 16; s >= 1; s >>= 1) {
            const bool hi = (lane & s) != 0;
            #pragma unroll
            for (int j = 0; j < s; j++) {
                ull mine  = hi ? v[j + s] : v[j];
                ull sent  = hi ? v[j]     : v[j + s];
                ull other = __shfl_xor_sync(0xFFFFFFFFu, sent, s);
                v[j] = addf32x2(mine, other);
            }
        }

        const int p = lane >> 3, r = lane & 7;
        float f0, f1;
        unpk2(v[0], f0, f1);   // batches 2p, 2p+1
        g_partial[((size_t)kc * BSZ + 2 * p)     * NDIM + n0 + r] = f0;
        g_partial[((size_t)kc * BSZ + 2 * p + 1) * NDIM + n0 + r] = f1;
    }
}

// out[b*NDIM+n] = sum over SPLITK partials (fully coalesced float4)
__global__ void asl_combine_kernel(float* __restrict__ out) {
    const int i = blockIdx.x * blockDim.x + threadIdx.x;   // float4 index
    const int total4 = BSZ * NDIM / 4;                     // 22016
    if (i < total4) {
        const float4* p4 = reinterpret_cast<const float4*>(g_partial);
        float4 o = make_float4(0.f, 0.f, 0.f, 0.f);
        #pragma unroll
        for (int m = 0; m < SPLITK; m++) {
            float4 a = p4[i + (size_t)m * total4];
            o.x += a.x; o.y += a.y; o.z += a.z; o.w += a.w;
        }
        reinterpret_cast<float4*>(out)[i] = o;
    }
}

extern "C" void kernel_launch(void* const* d_in, const int* in_sizes, int n_in,
                              void* d_out, int out_size) {
    const float* x = (const float*)d_in[0];
    const float* w = (const float*)d_in[1];
    if (n_in >= 2 && in_sizes[0] == NDIM * KDIM) {   // defensive order fix
        const float* t = x; x = w; w = t;
    }
    float* out = (float*)d_out;

    cudaFuncSetAttribute(asl_gemv_kernel,
                         cudaFuncAttributeMaxDynamicSharedMemorySize,
                         SMEM_BYTES);

    asl_gemv_kernel<<<NCTAS, THREADS, SMEM_BYTES>>>(x, w);

    const int total4 = BSZ * NDIM / 4;   // 22016
    asl_combine_kernel<<<(total4 + 127) / 128, 128>>>(out);
}